// round 6
// baseline (speedup 1.0000x reference)
#include <cuda_runtime.h>

// PCEN: smooth[t] = 0.975*smooth[t-1] + 0.025*x[t], smooth[0]=x[0]
//       out = (x * (smooth+1e-6)^-0.98 + 2)^0.5 - 2^0.5
//
// Exact single-read chained scan (decoupled lookback). Each block owns
// 64 rows x 128-sample chunk. It loads the chunk once (cp.async), computes
// the zero-init local EMA end value P_end, waits for the predecessor
// chunk's carry B (global flag, safe because predecessor blockIdx is
// lower and CTAs dispatch in id order), publishes
//   carry_next = 0.975^128 * B + P_end        (one FMA per row)
// then recomputes the true EMA from B and writes the transformed output
// with streaming stores. DRAM traffic = 128 MiB read + 128 MiB write,
// no lookback re-reads (R3-R5 showed time == DRAM_bytes / 4.93 TB/s).
// Flags are consumer-reset so graph replays start from a clean state.

namespace {

constexpr int T_LEN = 4096;
constexpr int CHUNK = 128;
constexpr int CPR   = T_LEN / CHUNK;   // 32 chunks per row
constexpr int RPB   = 64;              // rows per block == threads
constexpr int NROWS = 8192;            // 64 * 128 (fixed problem shape)
constexpr int NGRP  = NROWS / RPB;     // 128 row groups
constexpr int F4    = CHUNK / 4;       // 32 float4 per row
constexpr int STRIDE = F4 + 1;         // padded smem row stride (float4)

constexpr float A_STEP  = 0.975f;
constexpr float S_STEP  = 0.025f;
constexpr float A_CHUNK = 0.0391374f;  // 0.975^128

__device__ float g_carry[CPR * NROWS]; // carry INTO chunk c, row r
__device__ int   g_flag[CPR * NGRP];   // zero-init; set by producer, reset by consumer

__device__ __forceinline__ float pcen_pt(float xv, float sm) {
    float l = __log2f(sm + 1e-6f);                // MUFU.LG2
    float g = exp2f(-0.98f * l);                  // MUFU.EX2
    float v = fmaf(xv, g, 2.0f);
    return rsqrtf(v) * v - 1.41421356237309515f;  // MUFU.RSQ; v >= 2
}

__global__ __launch_bounds__(RPB, 6)
void pcen_kernel(const float* __restrict__ x, float* __restrict__ out) {
    __shared__ float4 buf[RPB * STRIDE];

    const int tid   = threadIdx.x;
    const int grp   = blockIdx.x % NGRP;
    const int chunk = blockIdx.x / NGRP;   // predecessor has lower blockIdx
    const int row0  = grp * RPB;

    const float* xbase = x + (size_t)row0 * T_LEN + chunk * CHUNK;

    // cooperative coalesced load of the whole 64x128 chunk into smem
    const int cr = tid >> 3;   // 0..7
    const int cf = tid & 7;    // 0..7
    #pragma unroll
    for (int j = 0; j < 4; ++j) {
        #pragma unroll
        for (int i = 0; i < 8; ++i) {
            int r = cr + 8 * i;
            int c4 = cf + 8 * j;
            const float* g = xbase + (size_t)r * T_LEN + c4 * 4;
            unsigned s = (unsigned)__cvta_generic_to_shared(&buf[r * STRIDE + c4]);
            asm volatile("cp.async.cg.shared.global [%0], [%1], 16;\n"
                         :: "r"(s), "l"(g));
        }
    }
    asm volatile("cp.async.commit_group;\n");
    asm volatile("cp.async.wait_group 0;\n");
    __syncthreads();

    const float4* my = &buf[tid * STRIDE];

    // pass 1: zero-init local EMA end value (chunk 0: exact init sm = x[0])
    float P = 0.0f;
    #pragma unroll
    for (int f = 0; f < F4; ++f) {
        float4 v = my[f];
        if (chunk == 0 && f == 0) P = v.x;
        else                      P = fmaf(A_STEP, P, S_STEP * v.x);
        P = fmaf(A_STEP, P, S_STEP * v.y);
        P = fmaf(A_STEP, P, S_STEP * v.z);
        P = fmaf(A_STEP, P, S_STEP * v.w);
    }

    // wait for predecessor carry
    float B = 0.0f;
    if (chunk > 0) {
        const int fidx = chunk * NGRP + grp;
        if (tid == 0) {
            while (atomicAdd(&g_flag[fidx], 0) == 0) { __nanosleep(40); }
        }
        __syncthreads();
        __threadfence();
        B = g_carry[(size_t)chunk * NROWS + row0 + tid];
        if (tid == 0) g_flag[fidx] = 0;   // reset for next graph replay
    }

    // publish carry for successor as early as possible
    if (chunk + 1 < CPR) {
        float carry_next = (chunk == 0) ? P : fmaf(A_CHUNK, B, P);
        g_carry[(size_t)(chunk + 1) * NROWS + row0 + tid] = carry_next;
        __threadfence();
        __syncthreads();   // all rows' carries globally visible
        if (tid == 0) atomicExch(&g_flag[(chunk + 1) * NGRP + grp], 1);
    }

    // pass 2: true EMA + PCEN transform, in place in smem
    float sm = B;
    float4* myw = &buf[tid * STRIDE];
    #pragma unroll
    for (int f = 0; f < F4; ++f) {
        float4 v = myw[f];
        if (chunk == 0 && f == 0) sm = v.x;
        else                      sm = fmaf(A_STEP, sm, S_STEP * v.x);
        float s0 = sm;
        sm = fmaf(A_STEP, sm, S_STEP * v.y);  float s1 = sm;
        sm = fmaf(A_STEP, sm, S_STEP * v.z);  float s2 = sm;
        sm = fmaf(A_STEP, sm, S_STEP * v.w);  float s3 = sm;
        float4 o;
        o.x = pcen_pt(v.x, s0);
        o.y = pcen_pt(v.y, s1);
        o.z = pcen_pt(v.z, s2);
        o.w = pcen_pt(v.w, s3);
        myw[f] = o;
    }
    __syncthreads();

    // cooperative coalesced streaming store
    float4* obase = reinterpret_cast<float4*>(out) +
                    (size_t)row0 * (T_LEN / 4) + chunk * F4;
    #pragma unroll
    for (int j = 0; j < 4; ++j) {
        #pragma unroll
        for (int i = 0; i < 8; ++i) {
            int r = cr + 8 * i;
            int c4 = cf + 8 * j;
            __stcs(&obase[(size_t)r * (T_LEN / 4) + c4], buf[r * STRIDE + c4]);
        }
    }
}

}  // namespace

extern "C" void kernel_launch(void* const* d_in, const int* in_sizes, int n_in,
                              void* d_out, int out_size) {
    const float* x = (const float*)d_in[0];
    float* out = (float*)d_out;
    int grid = CPR * NGRP;   // 4096 blocks; chunk-major => predecessors first
    pcen_kernel<<<grid, RPB>>>(x, out);
}

// round 7
// speedup vs baseline: 1.1163x; 1.1163x over previous
#include <cuda_runtime.h>

// PCEN: smooth[t] = 0.975*smooth[t-1] + 0.025*x[t], smooth[0]=x[0]
//       out = (x * (smooth+1e-6)^-0.98 + 2)^0.5 - 2^0.5
//
// Lookback-chunk scan (0.975^256 ~ 1.5e-3 decay -> ~1.5e-4 output error).
// Key change vs the 66us kernel: every global request is a 512B contiguous
// burst per row (32 lanes x 16B on ONE row) instead of 128B scattered
// across 8 rows -> 4 consecutive 128B lines per request, much better HBM
// page locality (R3-R5 were all pinned at 4.93 TB/s with 128B granularity).
// One warp per block (32 rows x 512-chunk), 2-stage cp.async pipeline into
// padded SMEM, serial per-row EMA from SMEM, in-place transform, 512B-burst
// streaming stores.

namespace {

constexpr int T_LEN  = 4096;
constexpr int CHUNK  = 512;
constexpr int LOOK   = 256;
constexpr int CPR    = T_LEN / CHUNK;   // 8
constexpr int RPB    = 32;              // rows per block == threads (1 warp)
constexpr int TILE   = 128;             // floats per tile per row (512B)
constexpr int TF4    = TILE / 4;        // 32
constexpr int PAD    = 1;
constexpr int STRIDE = TF4 + PAD;       // 33 float4 (33 mod 8 = 1: conflict-free)
constexpr int STAGES = 2;

__device__ __forceinline__ float pcen_pt(float xv, float sm) {
    float l = __log2f(sm + 1e-6f);                // MUFU.LG2
    float g = exp2f(-0.98f * l);                  // MUFU.EX2
    float v = fmaf(xv, g, 2.0f);
    return rsqrtf(v) * v - 1.41421356237309515f;  // MUFU.RSQ; v >= 2
}

__global__ __launch_bounds__(RPB, 6)
void pcen_kernel(const float* __restrict__ x, float* __restrict__ out,
                 int ngroups) {
    __shared__ float4 buf[STAGES][RPB * STRIDE];

    const int lane     = threadIdx.x;
    const int rowgroup = blockIdx.x % ngroups;
    const int chunk    = blockIdx.x / ngroups;
    const int row0     = rowgroup * RPB;

    const int cs = chunk * CHUNK;
    const int ws = max(0, cs - LOOK);               // window start (mult of TILE)
    const int n_tiles  = (cs + CHUNK - ws) / TILE;  // 4 (chunk 0) or 6
    const int out_from = (cs - ws) / TILE;          // 0 or 2

    const float* xbase = x + (size_t)row0 * T_LEN + ws;
    float4* obase = reinterpret_cast<float4*>(out) +
                    (size_t)row0 * (T_LEN / 4) + cs / 4;

    // each cp.async warp-instr: 32 lanes x 16B contiguous on ONE row = 512B burst
    auto issue_tile = [&](int k) {
        if (k < n_tiles) {
            const float* g0 = xbase + k * TILE + lane * 4;
            float4* b = buf[k % STAGES];
            #pragma unroll
            for (int r = 0; r < RPB; ++r) {
                const float* g = g0 + (size_t)r * T_LEN;
                unsigned s = (unsigned)__cvta_generic_to_shared(&b[r * STRIDE + lane]);
                asm volatile("cp.async.cg.shared.global [%0], [%1], 16;\n"
                             :: "r"(s), "l"(g));
            }
        }
        asm volatile("cp.async.commit_group;\n");
    };

    issue_tile(0);
    issue_tile(1);

    float sm = 0.0f;
    constexpr float S = 0.025f, OMS = 0.975f;

    for (int k = 0; k < n_tiles; ++k) {
        asm volatile("cp.async.wait_group 1;\n");   // tile k resident
        __syncwarp();

        float4* myrow = &buf[k % STAGES][lane * STRIDE];
        const bool emit = (k >= out_from);

        #pragma unroll 4
        for (int f = 0; f < TF4; ++f) {
            float4 v = myrow[f];
            if (k == 0 && f == 0) sm = v.x;          // exact init
            else                  sm = fmaf(OMS, sm, S * v.x);
            float s0 = sm;
            sm = fmaf(OMS, sm, S * v.y);  float s1 = sm;
            sm = fmaf(OMS, sm, S * v.z);  float s2 = sm;
            sm = fmaf(OMS, sm, S * v.w);  float s3 = sm;
            if (emit) {
                float4 o;
                o.x = pcen_pt(v.x, s0);
                o.y = pcen_pt(v.y, s1);
                o.z = pcen_pt(v.z, s2);
                o.w = pcen_pt(v.w, s3);
                myrow[f] = o;                        // in-place
            }
        }
        __syncwarp();

        if (emit) {
            const int ko = k - out_from;
            const float4* b = buf[k % STAGES];
            #pragma unroll
            for (int r = 0; r < RPB; ++r) {
                __stcs(&obase[(size_t)r * (T_LEN / 4) + ko * TF4 + lane],
                       b[r * STRIDE + lane]);
            }
            __syncwarp();
        }

        issue_tile(k + 2);   // refill slot k%2 (its compute/store is done)
    }
}

}  // namespace

extern "C" void kernel_launch(void* const* d_in, const int* in_sizes, int n_in,
                              void* d_out, int out_size) {
    const float* x = (const float*)d_in[0];
    float* out = (float*)d_out;
    int nrows = in_sizes[0] / T_LEN;        // 8192
    int ngroups = nrows / RPB;              // 256
    int grid = ngroups * CPR;               // 2048 blocks
    pcen_kernel<<<grid, RPB>>>(x, out, ngroups);
}

// round 8
// speedup vs baseline: 1.1908x; 1.0667x over previous
#include <cuda_runtime.h>

// PCEN: smooth[t] = 0.975*smooth[t-1] + 0.025*x[t], smooth[0]=x[0]
//       out = (x * (smooth+1e-6)^-0.98 + 2)^0.5 - 2^0.5
//
// Lookback-chunk scan (0.975^256 -> ~1.4e-4 output error, measured R7).
// Single-variable experiment vs the 66us R4 kernel: global requests are
// 256B contiguous per row (16 lanes x 16B on one row) instead of 128B,
// loads and stores both. Everything else matches R4: 64-thread blocks
// (64 rows x 512-chunk), 2-stage cp.async pipeline, padded SMEM, serial
// per-row EMA, in-place transform, cooperative streaming stores.

namespace {

constexpr int T_LEN  = 4096;
constexpr int CHUNK  = 512;
constexpr int LOOK   = 256;
constexpr int CPR    = T_LEN / CHUNK;   // 8
constexpr int RPB    = 64;              // rows per block == threads (2 warps)
constexpr int TILE   = 64;              // floats per tile per row (256B)
constexpr int TF4    = TILE / 4;        // 16
constexpr int STRIDE = TF4 + 1;         // 17 float4: conflict-free compute
constexpr int STAGES = 2;

__device__ __forceinline__ float pcen_pt(float xv, float sm) {
    float l = __log2f(sm + 1e-6f);                // MUFU.LG2
    float g = exp2f(-0.98f * l);                  // MUFU.EX2
    float v = fmaf(xv, g, 2.0f);
    return rsqrtf(v) * v - 1.41421356237309515f;  // MUFU.RSQ; v >= 2
}

__global__ __launch_bounds__(RPB, 6)
void pcen_kernel(const float* __restrict__ x, float* __restrict__ out,
                 int ngroups) {
    __shared__ float4 buf[STAGES][RPB * STRIDE];

    const int tid      = threadIdx.x;
    const int rowgroup = blockIdx.x % ngroups;
    const int chunk    = blockIdx.x / ngroups;
    const int row0     = rowgroup * RPB;

    const int cs = chunk * CHUNK;
    const int ws = max(0, cs - LOOK);               // window start (mult of TILE)
    const int n_tiles  = (cs + CHUNK - ws) / TILE;  // 8 (chunk 0) or 12
    const int out_from = (cs - ws) / TILE;          // 0 or 4

    const float* xbase = x + (size_t)row0 * T_LEN + ws;
    float4* obase = reinterpret_cast<float4*>(out) +
                    (size_t)row0 * (T_LEN / 4) + cs / 4;

    // 16 lanes cover 64 consecutive floats (256B) of ONE row.
    const int cr = tid >> 4;   // 0..3
    const int cf = tid & 15;   // 0..15

    auto issue_tile = [&](int k) {
        if (k < n_tiles) {
            const float* g0 = xbase + k * TILE + cf * 4;
            float4* b = buf[k & 1];
            #pragma unroll 8
            for (int i = 0; i < 16; ++i) {
                int r = cr + 4 * i;
                const float* g = g0 + (size_t)r * T_LEN;
                unsigned s = (unsigned)__cvta_generic_to_shared(&b[r * STRIDE + cf]);
                asm volatile("cp.async.cg.shared.global [%0], [%1], 16;\n"
                             :: "r"(s), "l"(g));
            }
        }
        asm volatile("cp.async.commit_group;\n");
    };

    issue_tile(0);
    issue_tile(1);

    float sm = 0.0f;
    constexpr float S = 0.025f, OMS = 0.975f;

    for (int k = 0; k < n_tiles; ++k) {
        asm volatile("cp.async.wait_group 1;\n");   // tile k resident
        __syncthreads();

        float4* myrow = &buf[k & 1][tid * STRIDE];
        const bool emit = (k >= out_from);

        #pragma unroll 4
        for (int f = 0; f < TF4; ++f) {
            float4 v = myrow[f];
            if (k == 0 && f == 0) sm = v.x;          // exact init
            else                  sm = fmaf(OMS, sm, S * v.x);
            float s0 = sm;
            sm = fmaf(OMS, sm, S * v.y);  float s1 = sm;
            sm = fmaf(OMS, sm, S * v.z);  float s2 = sm;
            sm = fmaf(OMS, sm, S * v.w);  float s3 = sm;
            if (emit) {
                float4 o;
                o.x = pcen_pt(v.x, s0);
                o.y = pcen_pt(v.y, s1);
                o.z = pcen_pt(v.z, s2);
                o.w = pcen_pt(v.w, s3);
                myrow[f] = o;                        // in-place
            }
        }
        __syncthreads();

        if (emit) {
            const int ko = k - out_from;
            const float4* b = buf[k & 1];
            #pragma unroll 8
            for (int i = 0; i < 16; ++i) {
                int r = cr + 4 * i;
                __stcs(&obase[(size_t)r * (T_LEN / 4) + ko * TF4 + cf],
                       b[r * STRIDE + cf]);
            }
            __syncthreads();
        }

        issue_tile(k + 2);   // refill slot k&1 (compute+store done above)
    }
}

}  // namespace

extern "C" void kernel_launch(void* const* d_in, const int* in_sizes, int n_in,
                              void* d_out, int out_size) {
    const float* x = (const float*)d_in[0];
    float* out = (float*)d_out;
    int nrows = in_sizes[0] / T_LEN;        // 8192
    int ngroups = nrows / RPB;              // 128
    int grid = ngroups * CPR;               // 1024 blocks
    pcen_kernel<<<grid, RPB>>>(x, out, ngroups);
}

// round 9
// speedup vs baseline: 1.5828x; 1.3292x over previous
#include <cuda_runtime.h>

// PCEN: smooth[t] = 0.975*smooth[t-1] + 0.025*x[t], smooth[0]=x[0]
//       out = (x * (smooth+1e-6)^-0.98 + 2)^0.5 - 2^0.5
//
// Warp-cooperative scan, no SMEM, no block barriers. One warp owns one
// (row, chunk). Per 128-sample step: coalesced float4 load into registers,
// lane-local Horner fold (4 elems -> affine offset b, decay A4=0.975^4),
// 5-round Kogge-Stone shuffle scan (constant decays 0.975^{4,8,16,32,64}),
// reconstruct 4 smooth values, PCEN transform, coalesced float4 streaming
// store. The serial dependency between steps is a single FMA
// (carry' = 0.975^128*carry + p31). CHUNK=2048 / LOOK=256 -> 1.125x reads.
// Chunk 0 is exact: carry=x[0] is the fixed point reproducing smooth[0]=x[0].

namespace {

constexpr int T_LEN = 4096;
constexpr int CHUNK = 2048;
constexpr int LOOK  = 256;
constexpr int CPR   = T_LEN / CHUNK;  // 2
constexpr int WPB   = 8;              // warps per block
constexpr int STEP  = 128;            // elements per warp-step

constexpr float A1 = 0.975f;
constexpr float S  = 0.025f;
constexpr float C1  = A1 * A1 * A1 * A1;   // 0.975^4
constexpr float C2  = C1 * C1;             // ^8
constexpr float C4  = C2 * C2;             // ^16
constexpr float C8  = C4 * C4;             // ^32
constexpr float C16 = C8 * C8;             // ^64
constexpr float C32 = C16 * C16;           // ^128

__device__ __forceinline__ float pcen_pt(float xv, float sm) {
    float l = __log2f(sm + 1e-6f);                // MUFU.LG2
    float g = exp2f(-0.98f * l);                  // MUFU.EX2
    float v = fmaf(xv, g, 2.0f);
    return rsqrtf(v) * v - 1.41421356237309515f;  // MUFU.RSQ; v >= 2
}

__global__ __launch_bounds__(WPB * 32)
void pcen_kernel(const float* __restrict__ x, float* __restrict__ out,
                 int nrows) {
    const int lane = threadIdx.x & 31;
    const int gw   = blockIdx.x * WPB + (threadIdx.x >> 5);
    const int chunk = gw % CPR;            // chunk fastest: lookback L2 locality
    const int row   = gw / CPR;
    if (row >= nrows) return;

    const float* xr = x + (size_t)row * T_LEN;
    float* orow = out + (size_t)row * T_LEN;

    const int cs = chunk * CHUNK;
    const int ws = (chunk == 0) ? 0 : cs - LOOK;
    const int ce = cs + CHUNK;

    // Al = C1^lane via binary expansion (compile-time constants)
    float Al = 1.0f;
    if (lane & 1)  Al *= C1;
    if (lane & 2)  Al *= C2;
    if (lane & 4)  Al *= C4;
    if (lane & 8)  Al *= C8;
    if (lane & 16) Al *= C16;
    const float Al1 = Al * C1;             // C1^(lane+1)

    const unsigned FULL = 0xffffffffu;

    float4 v = reinterpret_cast<const float4*>(xr + ws)[lane];
    float carry = __shfl_sync(FULL, v.x, 0);   // fixed point: smooth[ws]=x[ws]

    for (int t = ws; t < ce; t += STEP) {
        float4 vn = v;
        if (t + STEP < ce)
            vn = reinterpret_cast<const float4*>(xr + t + STEP)[lane];

        // lane-local affine offset: b = S*(A1^3 x0 + A1^2 x1 + A1 x2 + x3)
        float b = fmaf(A1, v.x, v.y);
        b = fmaf(A1, b, v.z);
        b = fmaf(A1, b, v.w);
        b *= S;

        // Kogge-Stone inclusive scan with decay C1 per lane-hop
        float p = b, tt;
        tt = __shfl_up_sync(FULL, p, 1);  if (lane >= 1)  p = fmaf(C1, tt, p);
        tt = __shfl_up_sync(FULL, p, 2);  if (lane >= 2)  p = fmaf(C2, tt, p);
        tt = __shfl_up_sync(FULL, p, 4);  if (lane >= 4)  p = fmaf(C4, tt, p);
        tt = __shfl_up_sync(FULL, p, 8);  if (lane >= 8)  p = fmaf(C8, tt, p);
        tt = __shfl_up_sync(FULL, p, 16); if (lane >= 16) p = fmaf(C16, tt, p);

        float pprev = __shfl_up_sync(FULL, p, 1);
        if (lane == 0) pprev = 0.0f;
        float p31 = __shfl_sync(FULL, p, 31);

        float s_in = fmaf(Al, carry, pprev);   // smooth state before this lane
        carry = fmaf(C32, carry, p31);         // serial chain: ONE FMA per step

        if (t >= cs) {
            float sm0 = fmaf(A1, s_in, S * v.x);
            float sm1 = fmaf(A1, sm0,  S * v.y);
            float sm2 = fmaf(A1, sm1,  S * v.z);
            float sm3 = fmaf(A1, sm2,  S * v.w);
            float4 o;
            o.x = pcen_pt(v.x, sm0);
            o.y = pcen_pt(v.y, sm1);
            o.z = pcen_pt(v.z, sm2);
            o.w = pcen_pt(v.w, sm3);
            __stcs(&reinterpret_cast<float4*>(orow + t)[lane], o);
        }
        v = vn;
    }
}

}  // namespace

extern "C" void kernel_launch(void* const* d_in, const int* in_sizes, int n_in,
                              void* d_out, int out_size) {
    const float* x = (const float*)d_in[0];
    float* out = (float*)d_out;
    int nrows = in_sizes[0] / T_LEN;            // 8192
    int nwarps = nrows * CPR;                   // 16384
    int blocks = (nwarps + WPB - 1) / WPB;      // 2048
    pcen_kernel<<<blocks, WPB * 32>>>(x, out, nrows);
}

// round 10
// speedup vs baseline: 1.5900x; 1.0045x over previous
#include <cuda_runtime.h>

// PCEN: smooth[t] = 0.975*smooth[t-1] + 0.025*x[t], smooth[0]=x[0]
//       out = (x / (smooth+1e-6)^0.98 + 2)^0.5 - 2^0.5
//
// Exact warp-cooperative scan: one warp owns one FULL row (T=4096, 32
// steps of 128). No SMEM, no barriers, no lookback, no chunk approximation.
// Per step: coalesced float4 load, lane-local Horner fold (4 elems ->
// affine offset, decay 0.975^4), 5-round Kogge-Stone shuffle scan,
// reconstruct 4 smooths, PCEN transform, coalesced float4 streaming store.
// Cross-step serial chain is ONE FMA (carry' = 0.975^128*carry + p31).
// 8192 warps ~= 55/SM: whole grid resident in one wave. Fixed 32-iteration
// loop unrolled x4 so address ALU collapses and 4 LDG.128s batch (MLP=4).

namespace {

constexpr int T_LEN = 4096;
constexpr int WPB   = 8;              // warps per block
constexpr int STEP  = 128;            // elements per warp-step
constexpr int NSTEP = T_LEN / STEP;   // 32

constexpr float A1 = 0.975f;
constexpr float S  = 0.025f;
constexpr float C1  = A1 * A1 * A1 * A1;   // 0.975^4
constexpr float C2  = C1 * C1;             // ^8
constexpr float C4  = C2 * C2;             // ^16
constexpr float C8  = C4 * C4;             // ^32
constexpr float C16 = C8 * C8;             // ^64
constexpr float C32 = C16 * C16;           // ^128

__device__ __forceinline__ float pcen_pt(float xv, float sm) {
    float l = __log2f(sm + 1e-6f);                // MUFU.LG2
    float g = exp2f(-0.98f * l);                  // MUFU.EX2
    float v = fmaf(xv, g, 2.0f);
    return rsqrtf(v) * v - 1.41421356237309515f;  // MUFU.RSQ; v >= 2
}

__global__ __launch_bounds__(WPB * 32)
void pcen_kernel(const float* __restrict__ x, float* __restrict__ out,
                 int nrows) {
    const int lane = threadIdx.x & 31;
    const int row  = blockIdx.x * WPB + (threadIdx.x >> 5);
    if (row >= nrows) return;

    const float4* __restrict__ xr =
        reinterpret_cast<const float4*>(x + (size_t)row * T_LEN) + lane;
    float4* __restrict__ orow =
        reinterpret_cast<float4*>(out + (size_t)row * T_LEN) + lane;

    // Al = C1^lane via binary expansion (compile-time constants)
    float Al = 1.0f;
    if (lane & 1)  Al *= C1;
    if (lane & 2)  Al *= C2;
    if (lane & 4)  Al *= C4;
    if (lane & 8)  Al *= C8;
    if (lane & 16) Al *= C16;

    const unsigned FULL = 0xffffffffu;

    float4 v = xr[0];
    float carry = __shfl_sync(FULL, v.x, 0);   // fixed point: smooth[0] = x[0]

    #pragma unroll 4
    for (int k = 0; k < NSTEP; ++k) {
        float4 vn = v;
        if (k + 1 < NSTEP) vn = xr[(k + 1) * (STEP / 4)];

        // lane-local affine offset: b = S*(A1^3 x0 + A1^2 x1 + A1 x2 + x3)
        float b = fmaf(A1, v.x, v.y);
        b = fmaf(A1, b, v.z);
        b = fmaf(A1, b, v.w);
        b *= S;

        // Kogge-Stone inclusive scan with decay C1 per lane-hop
        float p = b, tt;
        tt = __shfl_up_sync(FULL, p, 1);  if (lane >= 1)  p = fmaf(C1, tt, p);
        tt = __shfl_up_sync(FULL, p, 2);  if (lane >= 2)  p = fmaf(C2, tt, p);
        tt = __shfl_up_sync(FULL, p, 4);  if (lane >= 4)  p = fmaf(C4, tt, p);
        tt = __shfl_up_sync(FULL, p, 8);  if (lane >= 8)  p = fmaf(C8, tt, p);
        tt = __shfl_up_sync(FULL, p, 16); if (lane >= 16) p = fmaf(C16, tt, p);

        float pprev = __shfl_up_sync(FULL, p, 1);
        if (lane == 0) pprev = 0.0f;
        float p31 = __shfl_sync(FULL, p, 31);

        float s_in = fmaf(Al, carry, pprev);   // smooth state entering this lane
        carry = fmaf(C32, carry, p31);         // serial chain: ONE FMA per step

        float sm0 = fmaf(A1, s_in, S * v.x);
        float sm1 = fmaf(A1, sm0,  S * v.y);
        float sm2 = fmaf(A1, sm1,  S * v.z);
        float sm3 = fmaf(A1, sm2,  S * v.w);
        float4 o;
        o.x = pcen_pt(v.x, sm0);
        o.y = pcen_pt(v.y, sm1);
        o.z = pcen_pt(v.z, sm2);
        o.w = pcen_pt(v.w, sm3);
        __stcs(&orow[k * (STEP / 4)], o);

        v = vn;
    }
}

}  // namespace

extern "C" void kernel_launch(void* const* d_in, const int* in_sizes, int n_in,
                              void* d_out, int out_size) {
    const float* x = (const float*)d_in[0];
    float* out = (float*)d_out;
    int nrows = in_sizes[0] / T_LEN;            // 8192 warps, one per row
    int blocks = (nrows + WPB - 1) / WPB;       // 1024 blocks
    pcen_kernel<<<blocks, WPB * 32>>>(x, out, nrows);
}